// round 1
// baseline (speedup 1.0000x reference)
#include <cuda_runtime.h>
#include <math.h>

// Problem constants
#define BB   32      // batch
#define LL   1024    // label size
#define DG   1024    // graph dim
#define HH   1024    // hidden
#define OUTW (DG + HH)  // 2048

// Scratch: gate[b][l] post-sigmoid. 32*1024 floats = 128 KiB.
__device__ float g_gate[BB * LL];

// ---------------------------------------------------------------------------
// Kernel 1: gate = sigmoid(query @ W + b)
// Grid: (LL/32, BB/8) = (32, 4) blocks, 256 threads.
// Each block: 8 batches x 32 l-columns x full H=1024.
//   warp w handles h in [w*128, (w+1)*128), lane = l within the 32-tile.
//   query rows staged in smem; W loads coalesced (lane -> consecutive l).
// Cross-warp reduce via smem, then sigmoid + store.
// ---------------------------------------------------------------------------
__global__ __launch_bounds__(256, 1)
void gate_kernel(const float* __restrict__ query,
                 const float* __restrict__ W,
                 const float* __restrict__ bias)
{
    __shared__ float sq[8][HH];        // 32 KiB: 8 batch rows of query
    __shared__ float red[8][8][32];    // 8 KiB: [warp][batch][lane]

    const int tid  = threadIdx.x;
    const int warp = tid >> 5;
    const int lane = tid & 31;
    const int lt   = blockIdx.x;       // l-tile (0..31)
    const int bg   = blockIdx.y;       // batch group (0..3)

    // Stage 8 query rows into smem
    for (int i = tid; i < 8 * HH; i += 256) {
        int b = i >> 10;
        int h = i & (HH - 1);
        sq[b][h] = query[(bg * 8 + b) * HH + h];
    }
    __syncthreads();

    const int l = lt * 32 + lane;
    float acc0 = 0.f, acc1 = 0.f, acc2 = 0.f, acc3 = 0.f;
    float acc4 = 0.f, acc5 = 0.f, acc6 = 0.f, acc7 = 0.f;

    const int h0 = warp * 128;
    #pragma unroll 4
    for (int h = h0; h < h0 + 128; ++h) {
        float w = __ldg(&W[h * LL + l]);   // coalesced across lanes
        acc0 = fmaf(sq[0][h], w, acc0);
        acc1 = fmaf(sq[1][h], w, acc1);
        acc2 = fmaf(sq[2][h], w, acc2);
        acc3 = fmaf(sq[3][h], w, acc3);
        acc4 = fmaf(sq[4][h], w, acc4);
        acc5 = fmaf(sq[5][h], w, acc5);
        acc6 = fmaf(sq[6][h], w, acc6);
        acc7 = fmaf(sq[7][h], w, acc7);
    }

    red[warp][0][lane] = acc0;
    red[warp][1][lane] = acc1;
    red[warp][2][lane] = acc2;
    red[warp][3][lane] = acc3;
    red[warp][4][lane] = acc4;
    red[warp][5][lane] = acc5;
    red[warp][6][lane] = acc6;
    red[warp][7][lane] = acc7;
    __syncthreads();

    // 256 threads = (8 batch) x (32 lanes): sum across 8 warps
    const int b = warp;   // reuse warp index as batch-within-group
    float s = 0.f;
    #pragma unroll
    for (int w2 = 0; w2 < 8; ++w2) s += red[w2][b][lane];
    s += __ldg(&bias[l]);

    float g = 1.0f / (1.0f + __expf(-s));
    g_gate[(bg * 8 + b) * LL + l] = g;
}

// ---------------------------------------------------------------------------
// Kernel 2: streaming fuse.
// One block per (b, l) row: out[b][l][0:1024]   = gate[b][l] * graph[b][l][:]
//                           out[b][l][1024:2048] = query[b][:]
// 256 threads, float4 (16B) fully-coalesced accesses. 32768 blocks.
// graph: 128 MiB read; out: 256 MiB write; query/gate: L2-resident.
// ---------------------------------------------------------------------------
__global__ __launch_bounds__(256, 8)
void stream_kernel(const float4* __restrict__ graph,
                   const float4* __restrict__ query,
                   float4* __restrict__ out)
{
    const int bl  = blockIdx.x;          // b*LL + l
    const int b   = bl >> 10;
    const int tid = threadIdx.x;

    const float g = __ldg(&g_gate[bl]);  // uniform broadcast load

    const float4 v = graph[(long long)bl * (DG / 4) + tid];
    const float4 q = query[b * (HH / 4) + tid];

    float4* o = out + (long long)bl * (OUTW / 4);
    o[tid]              = make_float4(v.x * g, v.y * g, v.z * g, v.w * g);
    o[(DG / 4) + tid]   = q;
}

extern "C" void kernel_launch(void* const* d_in, const int* in_sizes, int n_in,
                              void* d_out, int out_size)
{
    const float* graph = (const float*)d_in[0];  // [32,1024,1024]
    const float* query = (const float*)d_in[1];  // [32,1024]
    const float* W     = (const float*)d_in[2];  // [1024,1024]
    const float* bias  = (const float*)d_in[3];  // [1024]
    float* out = (float*)d_out;                  // [32,1024,2048]

    dim3 ggrid(LL / 32, BB / 8);                 // (32, 4)
    gate_kernel<<<ggrid, 256>>>(query, W, bias);

    stream_kernel<<<BB * LL, 256>>>((const float4*)graph,
                                    (const float4*)query,
                                    (float4*)out);
    (void)in_sizes; (void)n_in; (void)out_size;
}

// round 2
// speedup vs baseline: 1.2385x; 1.2385x over previous
#include <cuda_runtime.h>
#include <math.h>

#define BB   32
#define LL   1024
#define DG   1024
#define HH   1024
#define OUTW (DG + HH)

__device__ float g_gate[BB * LL];

// ---------------------------------------------------------------------------
// Kernel 1: gate = sigmoid(query @ W + b)
// Grid (32 l-tiles, 4 batch-groups) = 128 blocks, 512 threads (16 warps).
// Warp w covers h in [w*64, w*64+64); lane -> l within 32-wide l-tile.
// Inner loop unrolled x8: 8 W loads in flight (MLP=8), then 64 FMAs.
// 4 warps/SMSP hide the remaining DRAM/L2 latency.
// ---------------------------------------------------------------------------
__global__ __launch_bounds__(512, 1)
void gate_kernel(const float* __restrict__ query,
                 const float* __restrict__ W,
                 const float* __restrict__ bias)
{
    __shared__ float sq[8 * HH];          // 32 KiB: 8 query rows (flat)
    __shared__ float red[16][8][32];      // 16 KiB: [warp][batch][lane]

    const int tid  = threadIdx.x;
    const int warp = tid >> 5;            // 0..15
    const int lane = tid & 31;
    const int lt   = blockIdx.x;          // l-tile 0..31
    const int bg   = blockIdx.y;          // batch group 0..3

    // Stage 8 query rows (contiguous 32 KiB) via float4
    {
        const float4* src = (const float4*)(query + bg * 8 * HH);
        float4*       dst = (float4*)sq;
        #pragma unroll
        for (int i = 0; i < 4; ++i)
            dst[tid + i * 512] = src[tid + i * 512];
    }
    __syncthreads();

    const int l = lt * 32 + lane;
    float acc0 = 0.f, acc1 = 0.f, acc2 = 0.f, acc3 = 0.f;
    float acc4 = 0.f, acc5 = 0.f, acc6 = 0.f, acc7 = 0.f;

    const int h0 = warp * 64;
    for (int hb = 0; hb < 64; hb += 8) {
        float w0 = __ldg(&W[(h0 + hb + 0) * LL + l]);
        float w1 = __ldg(&W[(h0 + hb + 1) * LL + l]);
        float w2 = __ldg(&W[(h0 + hb + 2) * LL + l]);
        float w3 = __ldg(&W[(h0 + hb + 3) * LL + l]);
        float w4 = __ldg(&W[(h0 + hb + 4) * LL + l]);
        float w5 = __ldg(&W[(h0 + hb + 5) * LL + l]);
        float w6 = __ldg(&W[(h0 + hb + 6) * LL + l]);
        float w7 = __ldg(&W[(h0 + hb + 7) * LL + l]);

        const float* q = sq + (h0 + hb);   // q[b*HH + j] below
        #pragma unroll
        for (int b = 0; b < 8; ++b) {
            const float* qb = q + b * HH;
            float a = (b==0)?acc0:(b==1)?acc1:(b==2)?acc2:(b==3)?acc3:
                      (b==4)?acc4:(b==5)?acc5:(b==6)?acc6:acc7;
            a = fmaf(qb[0], w0, a);
            a = fmaf(qb[1], w1, a);
            a = fmaf(qb[2], w2, a);
            a = fmaf(qb[3], w3, a);
            a = fmaf(qb[4], w4, a);
            a = fmaf(qb[5], w5, a);
            a = fmaf(qb[6], w6, a);
            a = fmaf(qb[7], w7, a);
            if      (b==0) acc0 = a; else if (b==1) acc1 = a;
            else if (b==2) acc2 = a; else if (b==3) acc3 = a;
            else if (b==4) acc4 = a; else if (b==5) acc5 = a;
            else if (b==6) acc6 = a; else            acc7 = a;
        }
    }

    red[warp][0][lane] = acc0;
    red[warp][1][lane] = acc1;
    red[warp][2][lane] = acc2;
    red[warp][3][lane] = acc3;
    red[warp][4][lane] = acc4;
    red[warp][5][lane] = acc5;
    red[warp][6][lane] = acc6;
    red[warp][7][lane] = acc7;
    __syncthreads();

    // First 256 threads: (8 batch) x (32 lanes), sum across 16 warps
    if (tid < 256) {
        const int b = tid >> 5;
        float s = 0.f;
        #pragma unroll
        for (int w2 = 0; w2 < 16; ++w2) s += red[w2][b][lane];
        s += __ldg(&bias[l]);
        float g = 1.0f / (1.0f + __expf(-s));
        g_gate[(bg * 8 + b) * LL + l] = g;
    }
}

// ---------------------------------------------------------------------------
// Kernel 2: streaming fuse. One block per (b,l) row; float4 coalesced.
// graph is read-once -> __ldcs (evict-first); out stores streamed (__stcs).
// ---------------------------------------------------------------------------
__global__ __launch_bounds__(256, 8)
void stream_kernel(const float4* __restrict__ graph,
                   const float4* __restrict__ query,
                   float4* __restrict__ out)
{
    const int bl  = blockIdx.x;
    const int b   = bl >> 10;
    const int tid = threadIdx.x;

    const float g = __ldg(&g_gate[bl]);

    const float4 v = __ldcs(&graph[(long long)bl * (DG / 4) + tid]);
    const float4 q = __ldg(&query[b * (HH / 4) + tid]);

    float4* o = out + (long long)bl * (OUTW / 4);
    __stcs(&o[tid],            make_float4(v.x * g, v.y * g, v.z * g, v.w * g));
    __stcs(&o[(DG / 4) + tid], q);
}

extern "C" void kernel_launch(void* const* d_in, const int* in_sizes, int n_in,
                              void* d_out, int out_size)
{
    const float* graph = (const float*)d_in[0];
    const float* query = (const float*)d_in[1];
    const float* W     = (const float*)d_in[2];
    const float* bias  = (const float*)d_in[3];
    float* out = (float*)d_out;

    dim3 ggrid(LL / 32, BB / 8);
    gate_kernel<<<ggrid, 512>>>(query, W, bias);

    stream_kernel<<<BB * LL, 256>>>((const float4*)graph,
                                    (const float4*)query,
                                    (float4*)out);
    (void)in_sizes; (void)n_in; (void)out_size;
}